// round 14
// baseline (speedup 1.0000x reference)
#include <cuda_runtime.h>
#include <cuda_fp16.h>
#include <cstdint>
#include <math.h>

#define BB 4
#define SS 2048
#define DD 1024
#define HH 1024
#define SCALEF 0.125f
#define MR (BB * SS)          // 8192

// ---------------- scratch (allocation-free rule) ----------------
__device__ float g_vT[BB * HH * SS];     // transposed V: [b][h][s]
__device__ float g_sc[BB * SS * SS];
__device__ float g_ctx[BB * SS * HH];
__device__ __align__(16) __half g_qh[MR * HH], g_ql[MR * HH];
__device__ __align__(16) __half g_kh[MR * HH], g_kl[MR * HH];
__device__ __align__(16) __half s_Wqh[HH * DD], s_Wql[HH * DD];
__device__ __align__(16) __half s_Wkh[HH * DD], s_Wkl[HH * DD];
__device__ __align__(16) __half s_Wvh[HH * DD], s_Wvl[HH * DD];
__device__ __align__(16) __half s_Woh[DD * HH], s_Wol[DD * HH];
__device__ float g_pm[BB * 8 * SS];
__device__ float g_ps[BB * 8 * SS];
__device__ float g_colM[BB * SS];
__device__ float g_colI[BB * SS];

// ---------------- helpers ----------------
__device__ __forceinline__ uint32_t smem_u32(const void* p) {
    uint32_t a;
    asm("{ .reg .u64 t; cvta.to.shared.u64 t, %1; cvt.u32.u64 %0, t; }" : "=r"(a) : "l"(p));
    return a;
}

#define LDSM4(r, a) \
    asm volatile("ldmatrix.sync.aligned.m8n8.x4.shared.b16 {%0,%1,%2,%3}, [%4];" \
        : "=r"((r)[0]), "=r"((r)[1]), "=r"((r)[2]), "=r"((r)[3]) : "r"(a))

__device__ __forceinline__ void mma16816(float* c, const uint32_t* a, const uint32_t* b) {
    asm volatile("mma.sync.aligned.m16n8k16.row.col.f32.f16.f16.f32 "
        "{%0,%1,%2,%3}, {%4,%5,%6,%7}, {%8,%9}, {%0,%1,%2,%3};"
        : "+f"(c[0]), "+f"(c[1]), "+f"(c[2]), "+f"(c[3])
        : "r"(a[0]), "r"(a[1]), "r"(a[2]), "r"(a[3]), "r"(b[0]), "r"(b[1]));
}

// split fp32x4 into hi fp16x4 + lo fp16x4 (exact residual)
__device__ __forceinline__ void cvt_split(float4 v, uint32_t& h01, uint32_t& h23,
                                          uint32_t& l01, uint32_t& l23) {
    __half2 a = __floats2half2_rn(v.x, v.y);
    __half2 b = __floats2half2_rn(v.z, v.w);
    float r0 = v.x - __half2float(__low2half(a));
    float r1 = v.y - __half2float(__high2half(a));
    float r2 = v.z - __half2float(__low2half(b));
    float r3 = v.w - __half2float(__high2half(b));
    __half2 c = __floats2half2_rn(r0, r1);
    __half2 d = __floats2half2_rn(r2, r3);
    h01 = *reinterpret_cast<uint32_t*>(&a);
    h23 = *reinterpret_cast<uint32_t*>(&b);
    l01 = *reinterpret_cast<uint32_t*>(&c);
    l23 = *reinterpret_cast<uint32_t*>(&d);
}
__device__ __forceinline__ void cvt_hi(float4 v, uint32_t& h01, uint32_t& h23) {
    __half2 a = __floats2half2_rn(v.x, v.y);
    __half2 b = __floats2half2_rn(v.z, v.w);
    h01 = *reinterpret_cast<uint32_t*>(&a);
    h23 = *reinterpret_cast<uint32_t*>(&b);
}
__device__ __forceinline__ void wr_split(__half* H, __half* L, long idx, float v0, float v1) {
    __half2 h = __floats2half2_rn(v0, v1);
    __half2 l = __floats2half2_rn(v0 - __low2float(h), v1 - __high2float(h));
    *reinterpret_cast<__half2*>(H + idx) = h;
    *reinterpret_cast<__half2*>(L + idx) = l;
}

// ---------------- fp32 -> hi/lo fp16 split: all 4 weights, one launch ----------------
__global__ __launch_bounds__(256) void split_w4(
    const float4* __restrict__ w0, __half2* __restrict__ h0p, __half2* __restrict__ l0p,
    const float4* __restrict__ w1, __half2* __restrict__ h1p, __half2* __restrict__ l1p,
    const float4* __restrict__ w2, __half2* __restrict__ h2p, __half2* __restrict__ l2p,
    const float4* __restrict__ w3, __half2* __restrict__ h3p, __half2* __restrict__ l3p,
    int n4)
{
    const float4* x; __half2* hi; __half2* lo;
    switch (blockIdx.y) {
        case 0: x = w0; hi = h0p; lo = l0p; break;
        case 1: x = w1; hi = h1p; lo = l1p; break;
        case 2: x = w2; hi = h2p; lo = l2p; break;
        default: x = w3; hi = h3p; lo = l3p; break;
    }
    int i = blockIdx.x * 256 + threadIdx.x;
    if (i >= n4) return;
    float4 v = x[i];
    __half2 a = __floats2half2_rn(v.x, v.y);
    __half2 b = __floats2half2_rn(v.z, v.w);
    __half2 c = __floats2half2_rn(v.x - __low2float(a), v.y - __high2float(a));
    __half2 d = __floats2half2_rn(v.z - __low2float(b), v.w - __high2float(b));
    hi[2 * i] = a; hi[2 * i + 1] = b;
    lo[2 * i] = c; lo[2 * i + 1] = d;
}

// ---------------- HMMA split-fp16 NT GEMM, tile 128x256x32, 512 threads ----------------
// C[m,n] = alpha * sum_k A[m,k] * B[n,k] (+ bias[n])
// 16 warps (2m x 8n), warp tile 64x32 -> 4 warps/SMSP for HMMA latency coverage.
// Pass-major MMA ordering; pass 3 reloads A-lo frags on the fly (register cap 128).
#define LROW 80
#define OFF_AL 10240              // A: 128 rows x 80B
#define OFF_BH 20480
#define OFF_BL 40960              // B: 256 rows x 80B
#define BUFSZ  61440
#define SMEM_SZ (2 * BUFSZ)
#define NT 512

template <int PASSES, int TRANSV, int APRE, int BPRE, int OUTSPLIT, int FUSESM>
__global__ __launch_bounds__(NT, 1) void gemm_hmma(
    const float* __restrict__ Af, const __half* __restrict__ APh, const __half* __restrict__ APl,
    const float* __restrict__ Bf, const __half* __restrict__ BPh, const __half* __restrict__ BPl,
    const float* __restrict__ bias, float* __restrict__ Cf,
    __half* __restrict__ COh, __half* __restrict__ COl,
    const float* __restrict__ cmp, const float* __restrict__ cip,
    int M, int N, int K, long sA, long sB, long sC, float alpha)
{
    extern __shared__ char smem[];
    const uint32_t sb = smem_u32(smem);
    const int tid  = threadIdx.x;
    const int lane = tid & 31;
    const int wid  = tid >> 5;
    const int wm   = wid & 1;     // 2 warps in m
    const int wn   = wid >> 1;    // 8 warps in n
    const long z   = blockIdx.z;

    const int rowBase = blockIdx.y * 128;
    const int colBase = blockIdx.x * 256;

    const float*  Apf = nullptr; const __half *Aph = nullptr, *Apl = nullptr;
    const float*  Bpf = nullptr; const __half *Bph = nullptr, *Bpl = nullptr;
    if (!APRE) Apf = Af + z * sA + (long)rowBase * K;
    else { Aph = APh + z * sA + (long)rowBase * K;
           if (PASSES == 3) Apl = APl + z * sA + (long)rowBase * K; }
    if (!BPRE) Bpf = Bf + z * sB + (long)colBase * K;
    else { Bph = BPh + z * sB + (long)colBase * K;
           Bpl = BPl + z * sB + (long)colBase * K; }
    const float* cmz = FUSESM ? cmp + z * SS : nullptr;
    const float* ciz = FUSESM ? cip + z * SS : nullptr;

    float4 pa[2], pb[4];
    uint4  pah, pal, pbh[2], pbl[2];

    auto loadAB = [&](int k0) {
        if (!APRE) {
#pragma unroll
            for (int h = 0; h < 2; h++) {
                int idx = tid + (h << 9);
                pa[h] = *reinterpret_cast<const float4*>(
                    Apf + (long)(idx >> 3) * K + k0 + ((idx & 7) << 2));
            }
        } else {
            long go = (long)(tid >> 2) * K + k0 + ((tid & 3) << 3);
            pah = *reinterpret_cast<const uint4*>(Aph + go);
            if (PASSES == 3) pal = *reinterpret_cast<const uint4*>(Apl + go);
        }
        if (!BPRE) {
#pragma unroll
            for (int h = 0; h < 4; h++) {
                int idx = tid + (h << 9);
                pb[h] = *reinterpret_cast<const float4*>(
                    Bpf + (long)(idx >> 3) * K + k0 + ((idx & 7) << 2));
            }
        } else {
#pragma unroll
            for (int h = 0; h < 2; h++) {
                int idx = tid + (h << 9);
                long go = (long)(idx >> 2) * K + k0 + ((idx & 3) << 3);
                pbh[h] = *reinterpret_cast<const uint4*>(Bph + go);
                pbl[h] = *reinterpret_cast<const uint4*>(Bpl + go);
            }
        }
    };

    auto stageAB = [&](char* dst, int k0) {
        if (!APRE) {
#pragma unroll
            for (int h = 0; h < 2; h++) {
                int idx = tid + (h << 9);
                int row = idx >> 3, c4 = (idx & 7) << 2;
                float4 v = pa[h];
                if (FUSESM) {
                    float4 cmv = *reinterpret_cast<const float4*>(cmz + k0 + c4);
                    v.x = __expf(v.x - cmv.x);
                    v.y = __expf(v.y - cmv.y);
                    v.z = __expf(v.z - cmv.z);
                    v.w = __expf(v.w - cmv.w);
                }
                uint32_t h01, h23, l01, l23;
                int off = row * LROW + c4 * 2;
                if (PASSES == 3) {
                    cvt_split(v, h01, h23, l01, l23);
                    *reinterpret_cast<uint2*>(dst + off)          = make_uint2(h01, h23);
                    *reinterpret_cast<uint2*>(dst + off + OFF_AL) = make_uint2(l01, l23);
                } else {
                    cvt_hi(v, h01, h23);
                    *reinterpret_cast<uint2*>(dst + off)          = make_uint2(h01, h23);
                }
            }
        } else {
            int off = (tid >> 2) * LROW + ((tid & 3) << 4);
            *reinterpret_cast<uint4*>(dst + off) = pah;
            if (PASSES == 3) *reinterpret_cast<uint4*>(dst + off + OFF_AL) = pal;
        }
        if (!BPRE) {
#pragma unroll
            for (int h = 0; h < 4; h++) {
                int idx = tid + (h << 9);
                int row = idx >> 3, c4 = (idx & 7) << 2;
                float4 v = pb[h];
                if (FUSESM) {
                    float4 civ = *reinterpret_cast<const float4*>(ciz + k0 + c4);
                    v.x *= civ.x; v.y *= civ.y; v.z *= civ.z; v.w *= civ.w;
                }
                uint32_t h01, h23, l01, l23;
                int off = row * LROW + c4 * 2;
                cvt_split(v, h01, h23, l01, l23);
                *reinterpret_cast<uint2*>(dst + off + OFF_BH) = make_uint2(h01, h23);
                *reinterpret_cast<uint2*>(dst + off + OFF_BL) = make_uint2(l01, l23);
            }
        } else {
#pragma unroll
            for (int h = 0; h < 2; h++) {
                int idx = tid + (h << 9);
                int off = (idx >> 2) * LROW + ((idx & 3) << 4);
                *reinterpret_cast<uint4*>(dst + off + OFF_BH) = pbh[h];
                *reinterpret_cast<uint4*>(dst + off + OFF_BL) = pbl[h];
            }
        }
    };

    float acc[4][4][4] = {};
    const int nch = K >> 5;

    loadAB(0);
    stageAB(smem, 0);
    __syncthreads();

    for (int c = 0; c < nch; c++) {
        if (c + 1 < nch) loadAB((c + 1) << 5);

        const uint32_t base = sb + (c & 1) * BUFSZ;
#pragma unroll
        for (int ks = 0; ks < 2; ks++) {
            uint32_t ah[4][4], bh[2][4], bl[2][4];
            const int kcA = ks * 16 + ((lane >> 4) << 3);
            const int mr  = wm * 64 + (lane & 15);
#pragma unroll
            for (int mt = 0; mt < 4; mt++)
                LDSM4(ah[mt], base + (mr + mt * 16) * LROW + kcA * 2);
            const int nr  = wn * 32 + (lane & 7) + ((lane >> 4) << 3);
            const int kcB = ks * 16 + (((lane >> 3) & 1) << 3);
#pragma unroll
            for (int np = 0; np < 2; np++) {
                uint32_t bd = base + OFF_BH + (nr + np * 16) * LROW + kcB * 2;
                LDSM4(bh[np], bd);
                LDSM4(bl[np], bd + (OFF_BL - OFF_BH));
            }
            // pass-major: hh, then hl, then lh (lh reloads A-lo on the fly)
#pragma unroll
            for (int mt = 0; mt < 4; mt++)
#pragma unroll
                for (int nt = 0; nt < 4; nt++)
                    mma16816(acc[mt][nt], ah[mt], &bh[nt >> 1][(nt & 1) * 2]);
#pragma unroll
            for (int mt = 0; mt < 4; mt++)
#pragma unroll
                for (int nt = 0; nt < 4; nt++)
                    mma16816(acc[mt][nt], ah[mt], &bl[nt >> 1][(nt & 1) * 2]);
            if (PASSES == 3) {
#pragma unroll
                for (int mt = 0; mt < 4; mt++) {
                    uint32_t al[4];
                    LDSM4(al, base + OFF_AL + (mr + mt * 16) * LROW + kcA * 2);
#pragma unroll
                    for (int nt = 0; nt < 4; nt++)
                        mma16816(acc[mt][nt], al, &bh[nt >> 1][(nt & 1) * 2]);
                }
            }
        }

        if (c + 1 < nch) {
            stageAB(smem + ((c + 1) & 1) * BUFSZ, (c + 1) << 5);
            __syncthreads();
        }
    }

    // epilogue
    float*  Cfz = Cf  ? Cf  + z * sC : nullptr;
    __half* Chz = COh ? COh + z * sC : nullptr;
    __half* Clz = COl ? COl + z * sC : nullptr;
#pragma unroll
    for (int mt = 0; mt < 4; mt++) {
        const int r0 = rowBase + wm * 64 + mt * 16 + (lane >> 2);
#pragma unroll
        for (int nt = 0; nt < 4; nt++) {
            const int c0 = colBase + wn * 32 + nt * 8 + (lane & 3) * 2;
            float v0 = acc[mt][nt][0] * alpha;
            float v1 = acc[mt][nt][1] * alpha;
            float v2 = acc[mt][nt][2] * alpha;
            float v3 = acc[mt][nt][3] * alpha;
            if (bias) {
                float b0 = __ldg(bias + c0), b1 = __ldg(bias + c0 + 1);
                v0 += b0; v1 += b1; v2 += b0; v3 += b1;
            }
            if (OUTSPLIT) {
                wr_split(Chz, Clz, (long)r0 * N + c0, v0, v1);
                wr_split(Chz, Clz, (long)(r0 + 8) * N + c0, v2, v3);
            } else if (!TRANSV) {
                *reinterpret_cast<float2*>(Cfz + (long)r0 * N + c0)       = make_float2(v0, v1);
                *reinterpret_cast<float2*>(Cfz + (long)(r0 + 8) * N + c0) = make_float2(v2, v3);
            } else {
                const int b0i = r0 >> 11, s0 = r0 & 2047;
                const int b1i = (r0 + 8) >> 11, s1 = (r0 + 8) & 2047;
                float* t0 = Cfz + (long)b0i * (HH * (long)SS) + s0;
                float* t1 = Cfz + (long)b1i * (HH * (long)SS) + s1;
                t0[(long)c0 * SS] = v0;       t0[(long)(c0 + 1) * SS] = v1;
                t1[(long)c0 * SS] = v2;       t1[(long)(c0 + 1) * SS] = v3;
            }
        }
    }
}

// ---------------- split softmax over QUERY axis ----------------
__global__ __launch_bounds__(256) void softmax_part(const float* __restrict__ sc,
                                                    float* __restrict__ pm, float* __restrict__ ps)
{
    const int col = blockIdx.x * 256 + threadIdx.x;
    const int seg = blockIdx.y, b = blockIdx.z;
    const float* p = sc + (long)b * SS * SS + (long)seg * 256 * SS + col;
    float m = -INFINITY, s = 0.f;
#pragma unroll 4
    for (int r = 0; r < 256; r++) {
        float v = p[(long)r * SS];
        float nm = fmaxf(m, v);
        s = s * __expf(m - nm) + __expf(v - nm);
        m = nm;
    }
    pm[((long)b * 8 + seg) * SS + col] = m;
    ps[((long)b * 8 + seg) * SS + col] = s;
}

__global__ __launch_bounds__(256) void softmax_comb(const float* __restrict__ pm,
                                                    const float* __restrict__ ps,
                                                    float* __restrict__ cm, float* __restrict__ ci)
{
    const int i = blockIdx.x * 256 + threadIdx.x;
    const int b = i >> 11, col = i & 2047;
    float M = -INFINITY;
#pragma unroll
    for (int s = 0; s < 8; s++) M = fmaxf(M, pm[((long)b * 8 + s) * SS + col]);
    float S = 0.f;
#pragma unroll
    for (int s = 0; s < 8; s++)
        S += ps[((long)b * 8 + s) * SS + col] * __expf(pm[((long)b * 8 + s) * SS + col] - M);
    cm[i] = M;
    ci[i] = 1.f / S;
}

// ---------------- launch ----------------
template <typename T>
static T* sym_addr(const void* sym) {
    void* p = nullptr;
    cudaGetSymbolAddress(&p, sym);
    return reinterpret_cast<T*>(p);
}

extern "C" void kernel_launch(void* const* d_in, const int* in_sizes, int n_in,
                              void* d_out, int out_size)
{
    const float* query = (const float*)d_in[0];
    const float* key   = (const float*)d_in[1];
    const float* value = (const float*)d_in[2];
    const float* Wq    = (const float*)d_in[3];
    const float* bq    = (const float*)d_in[4];
    const float* Wk    = (const float*)d_in[5];
    const float* bk    = (const float*)d_in[6];
    const float* Wv    = (const float*)d_in[7];
    const float* bv    = (const float*)d_in[8];
    const float* Wo    = (const float*)d_in[9];
    const float* bo    = (const float*)d_in[10];
    float* out = (float*)d_out;

    float* vT  = sym_addr<float>(g_vT);
    float* sc  = sym_addr<float>(g_sc);
    float* ctx = sym_addr<float>(g_ctx);
    __half* qh = sym_addr<__half>(g_qh);  __half* ql = sym_addr<__half>(g_ql);
    __half* kh = sym_addr<__half>(g_kh);  __half* kl = sym_addr<__half>(g_kl);
    __half* Wqh = sym_addr<__half>(s_Wqh); __half* Wql = sym_addr<__half>(s_Wql);
    __half* Wkh = sym_addr<__half>(s_Wkh); __half* Wkl = sym_addr<__half>(s_Wkl);
    __half* Wvh = sym_addr<__half>(s_Wvh); __half* Wvl = sym_addr<__half>(s_Wvl);
    __half* Woh = sym_addr<__half>(s_Woh); __half* Wol = sym_addr<__half>(s_Wol);
    float* pm = sym_addr<float>(g_pm);  float* ps = sym_addr<float>(g_ps);
    float* cm = sym_addr<float>(g_colM); float* ci = sym_addr<float>(g_colI);

    cudaFuncSetAttribute(gemm_hmma<3,0,0,1,1,0>, cudaFuncAttributeMaxDynamicSharedMemorySize, SMEM_SZ);
    cudaFuncSetAttribute(gemm_hmma<2,1,0,1,0,0>, cudaFuncAttributeMaxDynamicSharedMemorySize, SMEM_SZ);
    cudaFuncSetAttribute(gemm_hmma<3,0,1,1,0,0>, cudaFuncAttributeMaxDynamicSharedMemorySize, SMEM_SZ);
    cudaFuncSetAttribute(gemm_hmma<2,0,0,0,0,1>, cudaFuncAttributeMaxDynamicSharedMemorySize, SMEM_SZ);
    cudaFuncSetAttribute(gemm_hmma<2,0,0,1,0,0>, cudaFuncAttributeMaxDynamicSharedMemorySize, SMEM_SZ);

    const int M = BB * SS;   // 8192

    // 0) split all 4 weights in ONE launch
    const int nW4 = HH * DD / 4;
    split_w4<<<dim3(nW4 / 256, 4), 256>>>(
        (const float4*)Wq, (__half2*)Wqh, (__half2*)Wql,
        (const float4*)Wk, (__half2*)Wkh, (__half2*)Wkl,
        (const float4*)Wv, (__half2*)Wvh, (__half2*)Wvl,
        (const float4*)Wo, (__half2*)Woh, (__half2*)Wol, nW4);

    // 1) Projections: A = fp32 input, B = pre-split weights.
    dim3 gp(HH / 256, M / 128, 1);
    gemm_hmma<3,0,0,1,1,0><<<gp, NT, SMEM_SZ>>>(query, nullptr, nullptr, nullptr, Wqh, Wql,
                                                bq, nullptr, qh, ql, nullptr, nullptr,
                                                M, HH, DD, 0, 0, 0, 1.f);
    gemm_hmma<3,0,0,1,1,0><<<gp, NT, SMEM_SZ>>>(key, nullptr, nullptr, nullptr, Wkh, Wkl,
                                                bk, nullptr, kh, kl, nullptr, nullptr,
                                                M, HH, DD, 0, 0, 0, 1.f);
    gemm_hmma<2,1,0,1,0,0><<<gp, NT, SMEM_SZ>>>(value, nullptr, nullptr, nullptr, Wvh, Wvl,
                                                bv, vT, nullptr, nullptr, nullptr, nullptr,
                                                M, HH, DD, 0, 0, 0, 1.f);

    // 2) Scores: both operands pre-split.
    dim3 gs(SS / 256, SS / 128, BB);
    gemm_hmma<3,0,1,1,0,0><<<gs, NT, SMEM_SZ>>>(nullptr, qh, ql, nullptr, kh, kl,
                                                nullptr, sc, nullptr, nullptr, nullptr, nullptr,
                                                SS, SS, HH,
                                                (long)SS * HH, (long)SS * HH, (long)SS * SS, SCALEF);

    // 3) Softmax stats over the query axis (normalization fused into ctx GEMM)
    softmax_part<<<dim3(SS / 256, 8, BB), 256>>>(sc, pm, ps);
    softmax_comb<<<dim3(BB * SS / 256), 256>>>(pm, ps, cm, ci);

    // 4) Context with fused softmax: A-stage exp(sc - cm[k]), B-stage vT*ci[k]; 2-pass
    dim3 gc(HH / 256, SS / 128, BB);
    gemm_hmma<2,0,0,0,0,1><<<gc, NT, SMEM_SZ>>>(sc, nullptr, nullptr, vT, nullptr, nullptr,
                                                nullptr, ctx, nullptr, nullptr, cm, ci,
                                                SS, HH, SS,
                                                (long)SS * SS, (long)HH * SS, (long)SS * HH, 1.f);

    // 5) Output projection: B = pre-split Wo, 2-pass, fp32 out + bias
    dim3 go(DD / 256, M / 128, 1);
    gemm_hmma<2,0,0,1,0,0><<<go, NT, SMEM_SZ>>>(ctx, nullptr, nullptr, nullptr, Woh, Wol,
                                                bo, out, nullptr, nullptr, nullptr, nullptr,
                                                M, DD, HH, 0, 0, 0, 1.f);
}

// round 15
// speedup vs baseline: 1.1388x; 1.1388x over previous
#include <cuda_runtime.h>
#include <cuda_fp16.h>
#include <cstdint>
#include <math.h>

#define BB 4
#define SS 2048
#define DD 1024
#define HH 1024
#define SCALEF 0.125f
#define MR (BB * SS)          // 8192

// ---------------- scratch (allocation-free rule) ----------------
__device__ float g_vT[BB * HH * SS];     // transposed V: [b][h][s]
__device__ float g_sc[BB * SS * SS];
__device__ float g_ctx[BB * SS * HH];
__device__ __align__(16) __half g_qh[MR * HH], g_ql[MR * HH];
__device__ __align__(16) __half g_kh[MR * HH], g_kl[MR * HH];
__device__ __align__(16) __half s_Wqh[HH * DD], s_Wql[HH * DD];
__device__ __align__(16) __half s_Wkh[HH * DD], s_Wkl[HH * DD];
__device__ __align__(16) __half s_Wvh[HH * DD], s_Wvl[HH * DD];
__device__ __align__(16) __half s_Woh[DD * HH], s_Wol[DD * HH];
__device__ float g_pm[BB * 8 * SS];
__device__ float g_ps[BB * 8 * SS];
__device__ float g_colM[BB * SS];
__device__ float g_colI[BB * SS];

// ---------------- helpers ----------------
__device__ __forceinline__ uint32_t smem_u32(const void* p) {
    uint32_t a;
    asm("{ .reg .u64 t; cvta.to.shared.u64 t, %1; cvt.u32.u64 %0, t; }" : "=r"(a) : "l"(p));
    return a;
}

#define LDSM4(r, a) \
    asm volatile("ldmatrix.sync.aligned.m8n8.x4.shared.b16 {%0,%1,%2,%3}, [%4];" \
        : "=r"((r)[0]), "=r"((r)[1]), "=r"((r)[2]), "=r"((r)[3]) : "r"(a))

__device__ __forceinline__ void mma16816(float* c, const uint32_t* a, const uint32_t* b) {
    asm volatile("mma.sync.aligned.m16n8k16.row.col.f32.f16.f16.f32 "
        "{%0,%1,%2,%3}, {%4,%5,%6,%7}, {%8,%9}, {%0,%1,%2,%3};"
        : "+f"(c[0]), "+f"(c[1]), "+f"(c[2]), "+f"(c[3])
        : "r"(a[0]), "r"(a[1]), "r"(a[2]), "r"(a[3]), "r"(b[0]), "r"(b[1]));
}

// split fp32x4 into hi fp16x4 + lo fp16x4 (exact residual)
__device__ __forceinline__ void cvt_split(float4 v, uint32_t& h01, uint32_t& h23,
                                          uint32_t& l01, uint32_t& l23) {
    __half2 a = __floats2half2_rn(v.x, v.y);
    __half2 b = __floats2half2_rn(v.z, v.w);
    float r0 = v.x - __half2float(__low2half(a));
    float r1 = v.y - __half2float(__high2half(a));
    float r2 = v.z - __half2float(__low2half(b));
    float r3 = v.w - __half2float(__high2half(b));
    __half2 c = __floats2half2_rn(r0, r1);
    __half2 d = __floats2half2_rn(r2, r3);
    h01 = *reinterpret_cast<uint32_t*>(&a);
    h23 = *reinterpret_cast<uint32_t*>(&b);
    l01 = *reinterpret_cast<uint32_t*>(&c);
    l23 = *reinterpret_cast<uint32_t*>(&d);
}
__device__ __forceinline__ void cvt_hi(float4 v, uint32_t& h01, uint32_t& h23) {
    __half2 a = __floats2half2_rn(v.x, v.y);
    __half2 b = __floats2half2_rn(v.z, v.w);
    h01 = *reinterpret_cast<uint32_t*>(&a);
    h23 = *reinterpret_cast<uint32_t*>(&b);
}
__device__ __forceinline__ void wr_split(__half* H, __half* L, long idx, float v0, float v1) {
    __half2 h = __floats2half2_rn(v0, v1);
    __half2 l = __floats2half2_rn(v0 - __low2float(h), v1 - __high2float(h));
    *reinterpret_cast<__half2*>(H + idx) = h;
    *reinterpret_cast<__half2*>(L + idx) = l;
}

// ---------------- fp32 -> hi/lo fp16 split: all 4 weights, one launch ----------------
__global__ __launch_bounds__(256) void split_w4(
    const float4* __restrict__ w0, __half2* __restrict__ h0p, __half2* __restrict__ l0p,
    const float4* __restrict__ w1, __half2* __restrict__ h1p, __half2* __restrict__ l1p,
    const float4* __restrict__ w2, __half2* __restrict__ h2p, __half2* __restrict__ l2p,
    const float4* __restrict__ w3, __half2* __restrict__ h3p, __half2* __restrict__ l3p,
    int n4)
{
    const float4* x; __half2* hi; __half2* lo;
    switch (blockIdx.y) {
        case 0: x = w0; hi = h0p; lo = l0p; break;
        case 1: x = w1; hi = h1p; lo = l1p; break;
        case 2: x = w2; hi = h2p; lo = l2p; break;
        default: x = w3; hi = h3p; lo = l3p; break;
    }
    int i = blockIdx.x * 256 + threadIdx.x;
    if (i >= n4) return;
    float4 v = x[i];
    __half2 a = __floats2half2_rn(v.x, v.y);
    __half2 b = __floats2half2_rn(v.z, v.w);
    __half2 c = __floats2half2_rn(v.x - __low2float(a), v.y - __high2float(a));
    __half2 d = __floats2half2_rn(v.z - __low2float(b), v.w - __high2float(b));
    hi[2 * i] = a; hi[2 * i + 1] = b;
    lo[2 * i] = c; lo[2 * i + 1] = d;
}

// ---------------- HMMA split-fp16 NT GEMM, tile 128x256x32 (round-11 config) ----------------
// C[m,n] = alpha * sum_k A[m,k] * B[n,k] (+ bias[n])
// 8 warps (2m x 4n), warp tile 64x64; pass-major MMA ordering; register staging.
// MERGEQK: blockIdx.z selects primary (z=0) or secondary (z=1) operand set —
//          batches the Q and K projections into one launch to kill wave quantization.
// FUSESM: A = raw scores -> stage applies exp(a - cm[k]); B = vT -> stage applies *ci[k].
#define LROW 80
#define OFF_AL 10240              // A: 128 rows x 80B
#define OFF_BH 20480
#define OFF_BL 40960              // B: 256 rows x 80B
#define BUFSZ  61440
#define SMEM_SZ (2 * BUFSZ)

template <int PASSES, int TRANSV, int APRE, int BPRE, int OUTSPLIT, int FUSESM, int MERGEQK>
__global__ __launch_bounds__(256, 1) void gemm_hmma(
    const float* __restrict__ Af, const __half* __restrict__ APh, const __half* __restrict__ APl,
    const float* __restrict__ Bf, const __half* __restrict__ BPh, const __half* __restrict__ BPl,
    const float* __restrict__ bias, float* __restrict__ Cf,
    __half* __restrict__ COh, __half* __restrict__ COl,
    const float* __restrict__ cmp, const float* __restrict__ cip,
    const float* __restrict__ Af2, const __half* __restrict__ BPh2, const __half* __restrict__ BPl2,
    const float* __restrict__ bias2, __half* __restrict__ COh2, __half* __restrict__ COl2,
    int M, int N, int K, long sA, long sB, long sC, float alpha)
{
    extern __shared__ char smem[];
    const uint32_t sb = smem_u32(smem);
    const int tid  = threadIdx.x;
    const int lane = tid & 31;
    const int wid  = tid >> 5;
    const int wm   = wid & 1;
    const int wn   = wid >> 1;
    const long z   = blockIdx.z;

    if (MERGEQK && z == 1) {
        Af = Af2; BPh = BPh2; BPl = BPl2; bias = bias2; COh = COh2; COl = COl2;
    }
    const long zs = MERGEQK ? 0 : z;     // batch stride index (merged kernels are unbatched)

    const int rowBase = blockIdx.y * 128;
    const int colBase = blockIdx.x * 256;

    const int ldRow = tid >> 3;           // fp32 staging coords
    const int ldC4  = (tid & 7) << 2;

    const float*  Apf = nullptr; const __half *Aph = nullptr, *Apl = nullptr;
    const float*  Bpf = nullptr; const __half *Bph = nullptr, *Bpl = nullptr;
    if (!APRE) Apf = Af + zs * sA + (long)rowBase * K;
    else { Aph = APh + zs * sA + (long)rowBase * K;
           if (PASSES == 3) Apl = APl + zs * sA + (long)rowBase * K; }
    if (!BPRE) Bpf = Bf + zs * sB + (long)colBase * K;
    else { Bph = BPh + zs * sB + (long)colBase * K;
           Bpl = BPl + zs * sB + (long)colBase * K; }
    const float* cmz = FUSESM ? cmp + zs * SS : nullptr;
    const float* ciz = FUSESM ? cip + zs * SS : nullptr;

    float4 pa[4], pb[8];
    uint4  pah[2], pal[2], pbh[4], pbl[4];

    auto loadAB = [&](int k0) {
        if (!APRE) {
#pragma unroll
            for (int i = 0; i < 4; i++)
                pa[i] = *reinterpret_cast<const float4*>(Apf + (long)(ldRow + i * 32) * K + k0 + ldC4);
        } else {
#pragma unroll
            for (int h = 0; h < 2; h++) {
                int idx = tid + (h << 8);
                long go = (long)(idx >> 2) * K + k0 + ((idx & 3) << 3);
                pah[h] = *reinterpret_cast<const uint4*>(Aph + go);
                if (PASSES == 3) pal[h] = *reinterpret_cast<const uint4*>(Apl + go);
            }
        }
        if (!BPRE) {
#pragma unroll
            for (int i = 0; i < 8; i++)
                pb[i] = *reinterpret_cast<const float4*>(Bpf + (long)(ldRow + i * 32) * K + k0 + ldC4);
        } else {
#pragma unroll
            for (int h = 0; h < 4; h++) {
                int idx = tid + (h << 8);
                long go = (long)(idx >> 2) * K + k0 + ((idx & 3) << 3);
                pbh[h] = *reinterpret_cast<const uint4*>(Bph + go);
                pbl[h] = *reinterpret_cast<const uint4*>(Bpl + go);
            }
        }
    };

    auto stageAB = [&](char* dst, int k0) {
        if (!APRE) {
            float4 cmv;
            if (FUSESM) cmv = *reinterpret_cast<const float4*>(cmz + k0 + ldC4);
#pragma unroll
            for (int i = 0; i < 4; i++) {
                float4 v = pa[i];
                if (FUSESM) {
                    v.x = __expf(v.x - cmv.x);
                    v.y = __expf(v.y - cmv.y);
                    v.z = __expf(v.z - cmv.z);
                    v.w = __expf(v.w - cmv.w);
                }
                uint32_t h01, h23, l01, l23;
                int off = (ldRow + i * 32) * LROW + ldC4 * 2;
                if (PASSES == 3) {
                    cvt_split(v, h01, h23, l01, l23);
                    *reinterpret_cast<uint2*>(dst + off)          = make_uint2(h01, h23);
                    *reinterpret_cast<uint2*>(dst + off + OFF_AL) = make_uint2(l01, l23);
                } else {
                    cvt_hi(v, h01, h23);
                    *reinterpret_cast<uint2*>(dst + off)          = make_uint2(h01, h23);
                }
            }
        } else {
#pragma unroll
            for (int h = 0; h < 2; h++) {
                int idx = tid + (h << 8);
                int off = (idx >> 2) * LROW + ((idx & 3) << 4);
                *reinterpret_cast<uint4*>(dst + off) = pah[h];
                if (PASSES == 3) *reinterpret_cast<uint4*>(dst + off + OFF_AL) = pal[h];
            }
        }
        if (!BPRE) {
            float4 civ;
            if (FUSESM) civ = *reinterpret_cast<const float4*>(ciz + k0 + ldC4);
#pragma unroll
            for (int i = 0; i < 8; i++) {
                float4 v = pb[i];
                if (FUSESM) { v.x *= civ.x; v.y *= civ.y; v.z *= civ.z; v.w *= civ.w; }
                uint32_t h01, h23, l01, l23;
                int off = (ldRow + i * 32) * LROW + ldC4 * 2;
                cvt_split(v, h01, h23, l01, l23);
                *reinterpret_cast<uint2*>(dst + off + OFF_BH) = make_uint2(h01, h23);
                *reinterpret_cast<uint2*>(dst + off + OFF_BL) = make_uint2(l01, l23);
            }
        } else {
#pragma unroll
            for (int h = 0; h < 4; h++) {
                int idx = tid + (h << 8);
                int off = (idx >> 2) * LROW + ((idx & 3) << 4);
                *reinterpret_cast<uint4*>(dst + off + OFF_BH) = pbh[h];
                *reinterpret_cast<uint4*>(dst + off + OFF_BL) = pbl[h];
            }
        }
    };

    float acc[4][8][4] = {};
    const int nch = K >> 5;

    loadAB(0);
    stageAB(smem, 0);
    __syncthreads();

    for (int c = 0; c < nch; c++) {
        if (c + 1 < nch) loadAB((c + 1) << 5);

        const uint32_t base = sb + (c & 1) * BUFSZ;
#pragma unroll
        for (int ks = 0; ks < 2; ks++) {
            uint32_t ah[4][4], al[4][4], bh[4][4], bl[4][4];
            const int kcA = ks * 16 + ((lane >> 4) << 3);
            const int mr  = wm * 64 + (lane & 15);
#pragma unroll
            for (int mt = 0; mt < 4; mt++) {
                uint32_t ad = base + (mr + mt * 16) * LROW + kcA * 2;
                LDSM4(ah[mt], ad);
                if (PASSES == 3) LDSM4(al[mt], ad + OFF_AL);
            }
            const int nr  = wn * 64 + (lane & 7) + ((lane >> 4) << 3);
            const int kcB = ks * 16 + (((lane >> 3) & 1) << 3);
#pragma unroll
            for (int np = 0; np < 4; np++) {
                uint32_t bd = base + OFF_BH + (nr + np * 16) * LROW + kcB * 2;
                LDSM4(bh[np], bd);
                LDSM4(bl[np], bd + (OFF_BL - OFF_BH));
            }
            // pass-major ordering: consecutive MMAs never share an accumulator
#pragma unroll
            for (int mt = 0; mt < 4; mt++)
#pragma unroll
                for (int nt = 0; nt < 8; nt++)
                    mma16816(acc[mt][nt], ah[mt], &bh[nt >> 1][(nt & 1) * 2]);
#pragma unroll
            for (int mt = 0; mt < 4; mt++)
#pragma unroll
                for (int nt = 0; nt < 8; nt++)
                    mma16816(acc[mt][nt], ah[mt], &bl[nt >> 1][(nt & 1) * 2]);
            if (PASSES == 3) {
#pragma unroll
                for (int mt = 0; mt < 4; mt++)
#pragma unroll
                    for (int nt = 0; nt < 8; nt++)
                        mma16816(acc[mt][nt], al[mt], &bh[nt >> 1][(nt & 1) * 2]);
            }
        }

        if (c + 1 < nch) {
            stageAB(smem + ((c + 1) & 1) * BUFSZ, (c + 1) << 5);
            __syncthreads();
        }
    }

    // epilogue
    float*  Cfz = Cf  ? Cf  + zs * sC : nullptr;
    __half* Chz = COh ? COh + zs * sC : nullptr;
    __half* Clz = COl ? COl + zs * sC : nullptr;
#pragma unroll
    for (int mt = 0; mt < 4; mt++) {
        const int r0 = rowBase + wm * 64 + mt * 16 + (lane >> 2);
#pragma unroll
        for (int nt = 0; nt < 8; nt++) {
            const int c0 = colBase + wn * 64 + nt * 8 + (lane & 3) * 2;
            float v0 = acc[mt][nt][0] * alpha;
            float v1 = acc[mt][nt][1] * alpha;
            float v2 = acc[mt][nt][2] * alpha;
            float v3 = acc[mt][nt][3] * alpha;
            if (bias) {
                float b0 = __ldg(bias + c0), b1 = __ldg(bias + c0 + 1);
                v0 += b0; v1 += b1; v2 += b0; v3 += b1;
            }
            if (OUTSPLIT) {
                wr_split(Chz, Clz, (long)r0 * N + c0, v0, v1);
                wr_split(Chz, Clz, (long)(r0 + 8) * N + c0, v2, v3);
            } else if (!TRANSV) {
                *reinterpret_cast<float2*>(Cfz + (long)r0 * N + c0)       = make_float2(v0, v1);
                *reinterpret_cast<float2*>(Cfz + (long)(r0 + 8) * N + c0) = make_float2(v2, v3);
            } else {
                const int b0i = r0 >> 11, s0 = r0 & 2047;
                const int b1i = (r0 + 8) >> 11, s1 = (r0 + 8) & 2047;
                float* t0 = Cfz + (long)b0i * (HH * (long)SS) + s0;
                float* t1 = Cfz + (long)b1i * (HH * (long)SS) + s1;
                t0[(long)c0 * SS] = v0;       t0[(long)(c0 + 1) * SS] = v1;
                t1[(long)c0 * SS] = v2;       t1[(long)(c0 + 1) * SS] = v3;
            }
        }
    }
}

// ---------------- split softmax over QUERY axis ----------------
__global__ __launch_bounds__(256) void softmax_part(const float* __restrict__ sc,
                                                    float* __restrict__ pm, float* __restrict__ ps)
{
    const int col = blockIdx.x * 256 + threadIdx.x;
    const int seg = blockIdx.y, b = blockIdx.z;
    const float* p = sc + (long)b * SS * SS + (long)seg * 256 * SS + col;
    float m = -INFINITY, s = 0.f;
#pragma unroll 4
    for (int r = 0; r < 256; r++) {
        float v = p[(long)r * SS];
        float nm = fmaxf(m, v);
        s = s * __expf(m - nm) + __expf(v - nm);
        m = nm;
    }
    pm[((long)b * 8 + seg) * SS + col] = m;
    ps[((long)b * 8 + seg) * SS + col] = s;
}

__global__ __launch_bounds__(256) void softmax_comb(const float* __restrict__ pm,
                                                    const float* __restrict__ ps,
                                                    float* __restrict__ cm, float* __restrict__ ci)
{
    const int i = blockIdx.x * 256 + threadIdx.x;
    const int b = i >> 11, col = i & 2047;
    float M = -INFINITY;
#pragma unroll
    for (int s = 0; s < 8; s++) M = fmaxf(M, pm[((long)b * 8 + s) * SS + col]);
    float S = 0.f;
#pragma unroll
    for (int s = 0; s < 8; s++)
        S += ps[((long)b * 8 + s) * SS + col] * __expf(pm[((long)b * 8 + s) * SS + col] - M);
    cm[i] = M;
    ci[i] = 1.f / S;
}

// ---------------- launch ----------------
template <typename T>
static T* sym_addr(const void* sym) {
    void* p = nullptr;
    cudaGetSymbolAddress(&p, sym);
    return reinterpret_cast<T*>(p);
}

extern "C" void kernel_launch(void* const* d_in, const int* in_sizes, int n_in,
                              void* d_out, int out_size)
{
    const float* query = (const float*)d_in[0];
    const float* key   = (const float*)d_in[1];
    const float* value = (const float*)d_in[2];
    const float* Wq    = (const float*)d_in[3];
    const float* bq    = (const float*)d_in[4];
    const float* Wk    = (const float*)d_in[5];
    const float* bk    = (const float*)d_in[6];
    const float* Wv    = (const float*)d_in[7];
    const float* bv    = (const float*)d_in[8];
    const float* Wo    = (const float*)d_in[9];
    const float* bo    = (const float*)d_in[10];
    float* out = (float*)d_out;

    float* vT  = sym_addr<float>(g_vT);
    float* sc  = sym_addr<float>(g_sc);
    float* ctx = sym_addr<float>(g_ctx);
    __half* qh = sym_addr<__half>(g_qh);  __half* ql = sym_addr<__half>(g_ql);
    __half* kh = sym_addr<__half>(g_kh);  __half* kl = sym_addr<__half>(g_kl);
    __half* Wqh = sym_addr<__half>(s_Wqh); __half* Wql = sym_addr<__half>(s_Wql);
    __half* Wkh = sym_addr<__half>(s_Wkh); __half* Wkl = sym_addr<__half>(s_Wkl);
    __half* Wvh = sym_addr<__half>(s_Wvh); __half* Wvl = sym_addr<__half>(s_Wvl);
    __half* Woh = sym_addr<__half>(s_Woh); __half* Wol = sym_addr<__half>(s_Wol);
    float* pm = sym_addr<float>(g_pm);  float* ps = sym_addr<float>(g_ps);
    float* cm = sym_addr<float>(g_colM); float* ci = sym_addr<float>(g_colI);

    cudaFuncSetAttribute(gemm_hmma<3,0,0,1,1,0,1>, cudaFuncAttributeMaxDynamicSharedMemorySize, SMEM_SZ);
    cudaFuncSetAttribute(gemm_hmma<2,1,0,1,0,0,0>, cudaFuncAttributeMaxDynamicSharedMemorySize, SMEM_SZ);
    cudaFuncSetAttribute(gemm_hmma<3,0,1,1,0,0,0>, cudaFuncAttributeMaxDynamicSharedMemorySize, SMEM_SZ);
    cudaFuncSetAttribute(gemm_hmma<2,0,0,0,0,1,0>, cudaFuncAttributeMaxDynamicSharedMemorySize, SMEM_SZ);
    cudaFuncSetAttribute(gemm_hmma<2,0,0,1,0,0,0>, cudaFuncAttributeMaxDynamicSharedMemorySize, SMEM_SZ);

    const int M = BB * SS;   // 8192

    // 0) split all 4 weights in ONE launch
    const int nW4 = HH * DD / 4;
    split_w4<<<dim3(nW4 / 256, 4), 256>>>(
        (const float4*)Wq, (__half2*)Wqh, (__half2*)Wql,
        (const float4*)Wk, (__half2*)Wkh, (__half2*)Wkl,
        (const float4*)Wv, (__half2*)Wvh, (__half2*)Wvl,
        (const float4*)Wo, (__half2*)Woh, (__half2*)Wol, nW4);

    // 1) Q+K projections MERGED into one launch (grid.z: 0=Q, 1=K) — kills wave quantization.
    dim3 gqk(HH / 256, M / 128, 2);
    gemm_hmma<3,0,0,1,1,0,1><<<gqk, 256, SMEM_SZ>>>(
        query, nullptr, nullptr, nullptr, Wqh, Wql, bq, nullptr, qh, ql, nullptr, nullptr,
        key, Wkh, Wkl, bk, kh, kl,
        M, HH, DD, 0, 0, 0, 1.f);

    //    V projection (2-pass, vT scatter)
    dim3 gp(HH / 256, M / 128, 1);
    gemm_hmma<2,1,0,1,0,0,0><<<gp, 256, SMEM_SZ>>>(
        value, nullptr, nullptr, nullptr, Wvh, Wvl, bv, vT, nullptr, nullptr, nullptr, nullptr,
        nullptr, nullptr, nullptr, nullptr, nullptr, nullptr,
        M, HH, DD, 0, 0, 0, 1.f);

    // 2) Scores: both operands pre-split.
    dim3 gs(SS / 256, SS / 128, BB);
    gemm_hmma<3,0,1,1,0,0,0><<<gs, 256, SMEM_SZ>>>(
        nullptr, qh, ql, nullptr, kh, kl, nullptr, sc, nullptr, nullptr, nullptr, nullptr,
        nullptr, nullptr, nullptr, nullptr, nullptr, nullptr,
        SS, SS, HH, (long)SS * HH, (long)SS * HH, (long)SS * SS, SCALEF);

    // 3) Softmax stats over the query axis (normalization fused into ctx GEMM)
    softmax_part<<<dim3(SS / 256, 8, BB), 256>>>(sc, pm, ps);
    softmax_comb<<<dim3(BB * SS / 256), 256>>>(pm, ps, cm, ci);

    // 4) Context with fused softmax: A-stage exp(sc - cm[k]), B-stage vT*ci[k]; 2-pass
    dim3 gc(HH / 256, SS / 128, BB);
    gemm_hmma<2,0,0,0,0,1,0><<<gc, 256, SMEM_SZ>>>(
        sc, nullptr, nullptr, vT, nullptr, nullptr, nullptr, ctx, nullptr, nullptr, cm, ci,
        nullptr, nullptr, nullptr, nullptr, nullptr, nullptr,
        SS, HH, SS, (long)SS * SS, (long)HH * SS, (long)SS * HH, 1.f);

    // 5) Output projection: B = pre-split Wo, 2-pass, fp32 out + bias
    dim3 go(DD / 256, M / 128, 1);
    gemm_hmma<2,0,0,1,0,0,0><<<go, 256, SMEM_SZ>>>(
        ctx, nullptr, nullptr, nullptr, Woh, Wol, bo, out, nullptr, nullptr, nullptr, nullptr,
        nullptr, nullptr, nullptr, nullptr, nullptr, nullptr,
        M, DD, HH, 0, 0, 0, 1.f);
}

// round 16
// speedup vs baseline: 1.2748x; 1.1194x over previous
#include <cuda_runtime.h>
#include <cuda_fp16.h>
#include <cstdint>
#include <math.h>

#define BB 4
#define SS 2048
#define DD 1024
#define HH 1024
#define SCALEF 0.125f
#define MR (BB * SS)          // 8192

// ---------------- scratch (allocation-free rule) ----------------
__device__ float g_vT[BB * HH * SS];     // transposed V: [b][h][s]
__device__ float g_sc[BB * SS * SS];
__device__ float g_ctx[BB * SS * HH];
__device__ __align__(16) __half g_qh[MR * HH], g_ql[MR * HH];
__device__ __align__(16) __half g_kh[MR * HH], g_kl[MR * HH];
__device__ __align__(16) __half s_Wqh[HH * DD], s_Wql[HH * DD];
__device__ __align__(16) __half s_Wkh[HH * DD], s_Wkl[HH * DD];
__device__ __align__(16) __half s_Wvh[HH * DD], s_Wvl[HH * DD];
__device__ __align__(16) __half s_Woh[DD * HH], s_Wol[DD * HH];
__device__ float g_pm[BB * 8 * SS];
__device__ float g_ps[BB * 8 * SS];
__device__ float g_colM[BB * SS];
__device__ float g_colI[BB * SS];

// ---------------- helpers ----------------
__device__ __forceinline__ uint32_t smem_u32(const void* p) {
    uint32_t a;
    asm("{ .reg .u64 t; cvta.to.shared.u64 t, %1; cvt.u32.u64 %0, t; }" : "=r"(a) : "l"(p));
    return a;
}

#define LDSM4(r, a) \
    asm volatile("ldmatrix.sync.aligned.m8n8.x4.shared.b16 {%0,%1,%2,%3}, [%4];" \
        : "=r"((r)[0]), "=r"((r)[1]), "=r"((r)[2]), "=r"((r)[3]) : "r"(a))

__device__ __forceinline__ void mma16816(float* c, const uint32_t* a, const uint32_t* b) {
    asm volatile("mma.sync.aligned.m16n8k16.row.col.f32.f16.f16.f32 "
        "{%0,%1,%2,%3}, {%4,%5,%6,%7}, {%8,%9}, {%0,%1,%2,%3};"
        : "+f"(c[0]), "+f"(c[1]), "+f"(c[2]), "+f"(c[3])
        : "r"(a[0]), "r"(a[1]), "r"(a[2]), "r"(a[3]), "r"(b[0]), "r"(b[1]));
}

// split fp32x4 into hi fp16x4 + lo fp16x4 (exact residual)
__device__ __forceinline__ void cvt_split(float4 v, uint32_t& h01, uint32_t& h23,
                                          uint32_t& l01, uint32_t& l23) {
    __half2 a = __floats2half2_rn(v.x, v.y);
    __half2 b = __floats2half2_rn(v.z, v.w);
    float r0 = v.x - __half2float(__low2half(a));
    float r1 = v.y - __half2float(__high2half(a));
    float r2 = v.z - __half2float(__low2half(b));
    float r3 = v.w - __half2float(__high2half(b));
    __half2 c = __floats2half2_rn(r0, r1);
    __half2 d = __floats2half2_rn(r2, r3);
    h01 = *reinterpret_cast<uint32_t*>(&a);
    h23 = *reinterpret_cast<uint32_t*>(&b);
    l01 = *reinterpret_cast<uint32_t*>(&c);
    l23 = *reinterpret_cast<uint32_t*>(&d);
}
__device__ __forceinline__ void cvt_hi(float4 v, uint32_t& h01, uint32_t& h23) {
    __half2 a = __floats2half2_rn(v.x, v.y);
    __half2 b = __floats2half2_rn(v.z, v.w);
    h01 = *reinterpret_cast<uint32_t*>(&a);
    h23 = *reinterpret_cast<uint32_t*>(&b);
}
__device__ __forceinline__ void wr_split(__half* H, __half* L, long idx, float v0, float v1) {
    __half2 h = __floats2half2_rn(v0, v1);
    __half2 l = __floats2half2_rn(v0 - __low2float(h), v1 - __high2float(h));
    *reinterpret_cast<__half2*>(H + idx) = h;
    *reinterpret_cast<__half2*>(L + idx) = l;
}

// ---------------- fp32 -> hi/lo fp16 split: all 4 weights, one launch ----------------
__global__ __launch_bounds__(256) void split_w4(
    const float4* __restrict__ w0, __half2* __restrict__ h0p, __half2* __restrict__ l0p,
    const float4* __restrict__ w1, __half2* __restrict__ h1p, __half2* __restrict__ l1p,
    const float4* __restrict__ w2, __half2* __restrict__ h2p, __half2* __restrict__ l2p,
    const float4* __restrict__ w3, __half2* __restrict__ h3p, __half2* __restrict__ l3p,
    int n4)
{
    const float4* x; __half2* hi; __half2* lo;
    switch (blockIdx.y) {
        case 0: x = w0; hi = h0p; lo = l0p; break;
        case 1: x = w1; hi = h1p; lo = l1p; break;
        case 2: x = w2; hi = h2p; lo = l2p; break;
        default: x = w3; hi = h3p; lo = l3p; break;
    }
    int i = blockIdx.x * 256 + threadIdx.x;
    if (i >= n4) return;
    float4 v = x[i];
    __half2 a = __floats2half2_rn(v.x, v.y);
    __half2 b = __floats2half2_rn(v.z, v.w);
    __half2 c = __floats2half2_rn(v.x - __low2float(a), v.y - __high2float(a));
    __half2 d = __floats2half2_rn(v.z - __low2float(b), v.w - __high2float(b));
    hi[2 * i] = a; hi[2 * i + 1] = b;
    lo[2 * i] = c; lo[2 * i + 1] = d;
}

// ---------------- HMMA split-fp16 NT GEMM, tile 128x256x32 ----------------
// C[m,n] = alpha * sum_k A[m,k] * B[n,k] (+ bias[n])
// 8 warps (2m x 4n), warp tile 64x64; pass-major MMA ordering.
// FUSESM: A = raw scores -> stage applies exp(a - cm[k]); B = vT -> stage applies *ci[k].
#define LROW 80
#define OFF_AL 10240              // A: 128 rows x 80B
#define OFF_BH 20480
#define OFF_BL 40960              // B: 256 rows x 80B
#define BUFSZ  61440
#define SMEM_SZ (2 * BUFSZ)

template <int PASSES, int TRANSV, int APRE, int BPRE, int OUTSPLIT, int FUSESM>
__global__ __launch_bounds__(256, 1) void gemm_hmma(
    const float* __restrict__ Af, const __half* __restrict__ APh, const __half* __restrict__ APl,
    const float* __restrict__ Bf, const __half* __restrict__ BPh, const __half* __restrict__ BPl,
    const float* __restrict__ bias, float* __restrict__ Cf,
    __half* __restrict__ COh, __half* __restrict__ COl,
    const float* __restrict__ cmp, const float* __restrict__ cip,
    int M, int N, int K, long sA, long sB, long sC, float alpha)
{
    extern __shared__ char smem[];
    const uint32_t sb = smem_u32(smem);
    const int tid  = threadIdx.x;
    const int lane = tid & 31;
    const int wid  = tid >> 5;
    const int wm   = wid & 1;
    const int wn   = wid >> 1;
    const long z   = blockIdx.z;

    const int rowBase = blockIdx.y * 128;
    const int colBase = blockIdx.x * 256;

    const int ldRow = tid >> 3;           // fp32 staging coords
    const int ldC4  = (tid & 7) << 2;

    const float*  Apf = nullptr; const __half *Aph = nullptr, *Apl = nullptr;
    const float*  Bpf = nullptr; const __half *Bph = nullptr, *Bpl = nullptr;
    if (!APRE) Apf = Af + z * sA + (long)rowBase * K;
    else { Aph = APh + z * sA + (long)rowBase * K;
           if (PASSES == 3) Apl = APl + z * sA + (long)rowBase * K; }
    if (!BPRE) Bpf = Bf + z * sB + (long)colBase * K;
    else { Bph = BPh + z * sB + (long)colBase * K;
           Bpl = BPl + z * sB + (long)colBase * K; }
    const float* cmz = FUSESM ? cmp + z * SS : nullptr;
    const float* ciz = FUSESM ? cip + z * SS : nullptr;

    float4 pa[4], pb[8];
    uint4  pah[2], pal[2], pbh[4], pbl[4];

    auto loadAB = [&](int k0) {
        if (!APRE) {
#pragma unroll
            for (int i = 0; i < 4; i++)
                pa[i] = *reinterpret_cast<const float4*>(Apf + (long)(ldRow + i * 32) * K + k0 + ldC4);
        } else {
#pragma unroll
            for (int h = 0; h < 2; h++) {
                int idx = tid + (h << 8);
                long go = (long)(idx >> 2) * K + k0 + ((idx & 3) << 3);
                pah[h] = *reinterpret_cast<const uint4*>(Aph + go);
                if (PASSES == 3) pal[h] = *reinterpret_cast<const uint4*>(Apl + go);
            }
        }
        if (!BPRE) {
#pragma unroll
            for (int i = 0; i < 8; i++)
                pb[i] = *reinterpret_cast<const float4*>(Bpf + (long)(ldRow + i * 32) * K + k0 + ldC4);
        } else {
#pragma unroll
            for (int h = 0; h < 4; h++) {
                int idx = tid + (h << 8);
                long go = (long)(idx >> 2) * K + k0 + ((idx & 3) << 3);
                pbh[h] = *reinterpret_cast<const uint4*>(Bph + go);
                pbl[h] = *reinterpret_cast<const uint4*>(Bpl + go);
            }
        }
    };

    auto stageAB = [&](char* dst, int k0) {
        if (!APRE) {
            float4 cmv;
            if (FUSESM) cmv = *reinterpret_cast<const float4*>(cmz + k0 + ldC4);
#pragma unroll
            for (int i = 0; i < 4; i++) {
                float4 v = pa[i];
                if (FUSESM) {
                    v.x = __expf(v.x - cmv.x);
                    v.y = __expf(v.y - cmv.y);
                    v.z = __expf(v.z - cmv.z);
                    v.w = __expf(v.w - cmv.w);
                }
                uint32_t h01, h23, l01, l23;
                int off = (ldRow + i * 32) * LROW + ldC4 * 2;
                if (PASSES == 3) {
                    cvt_split(v, h01, h23, l01, l23);
                    *reinterpret_cast<uint2*>(dst + off)          = make_uint2(h01, h23);
                    *reinterpret_cast<uint2*>(dst + off + OFF_AL) = make_uint2(l01, l23);
                } else {
                    cvt_hi(v, h01, h23);
                    *reinterpret_cast<uint2*>(dst + off)          = make_uint2(h01, h23);
                }
            }
        } else {
#pragma unroll
            for (int h = 0; h < 2; h++) {
                int idx = tid + (h << 8);
                int off = (idx >> 2) * LROW + ((idx & 3) << 4);
                *reinterpret_cast<uint4*>(dst + off) = pah[h];
                if (PASSES == 3) *reinterpret_cast<uint4*>(dst + off + OFF_AL) = pal[h];
            }
        }
        if (!BPRE) {
            float4 civ;
            if (FUSESM) civ = *reinterpret_cast<const float4*>(ciz + k0 + ldC4);
#pragma unroll
            for (int i = 0; i < 8; i++) {
                float4 v = pb[i];
                if (FUSESM) { v.x *= civ.x; v.y *= civ.y; v.z *= civ.z; v.w *= civ.w; }
                uint32_t h01, h23, l01, l23;
                int off = (ldRow + i * 32) * LROW + ldC4 * 2;
                cvt_split(v, h01, h23, l01, l23);
                *reinterpret_cast<uint2*>(dst + off + OFF_BH) = make_uint2(h01, h23);
                *reinterpret_cast<uint2*>(dst + off + OFF_BL) = make_uint2(l01, l23);
            }
        } else {
#pragma unroll
            for (int h = 0; h < 4; h++) {
                int idx = tid + (h << 8);
                int off = (idx >> 2) * LROW + ((idx & 3) << 4);
                *reinterpret_cast<uint4*>(dst + off + OFF_BH) = pbh[h];
                *reinterpret_cast<uint4*>(dst + off + OFF_BL) = pbl[h];
            }
        }
    };

    float acc[4][8][4] = {};
    const int nch = K >> 5;

    loadAB(0);
    stageAB(smem, 0);
    __syncthreads();

    for (int c = 0; c < nch; c++) {
        if (c + 1 < nch) loadAB((c + 1) << 5);

        const uint32_t base = sb + (c & 1) * BUFSZ;
#pragma unroll
        for (int ks = 0; ks < 2; ks++) {
            uint32_t ah[4][4], al[4][4], bh[4][4], bl[4][4];
            const int kcA = ks * 16 + ((lane >> 4) << 3);
            const int mr  = wm * 64 + (lane & 15);
#pragma unroll
            for (int mt = 0; mt < 4; mt++) {
                uint32_t ad = base + (mr + mt * 16) * LROW + kcA * 2;
                LDSM4(ah[mt], ad);
                if (PASSES == 3) LDSM4(al[mt], ad + OFF_AL);
            }
            const int nr  = wn * 64 + (lane & 7) + ((lane >> 4) << 3);
            const int kcB = ks * 16 + (((lane >> 3) & 1) << 3);
#pragma unroll
            for (int np = 0; np < 4; np++) {
                uint32_t bd = base + OFF_BH + (nr + np * 16) * LROW + kcB * 2;
                LDSM4(bh[np], bd);
                LDSM4(bl[np], bd + (OFF_BL - OFF_BH));
            }
            // pass-major ordering: consecutive MMAs never share an accumulator
#pragma unroll
            for (int mt = 0; mt < 4; mt++)
#pragma unroll
                for (int nt = 0; nt < 8; nt++)
                    mma16816(acc[mt][nt], ah[mt], &bh[nt >> 1][(nt & 1) * 2]);
#pragma unroll
            for (int mt = 0; mt < 4; mt++)
#pragma unroll
                for (int nt = 0; nt < 8; nt++)
                    mma16816(acc[mt][nt], ah[mt], &bl[nt >> 1][(nt & 1) * 2]);
            if (PASSES == 3) {
#pragma unroll
                for (int mt = 0; mt < 4; mt++)
#pragma unroll
                    for (int nt = 0; nt < 8; nt++)
                        mma16816(acc[mt][nt], al[mt], &bh[nt >> 1][(nt & 1) * 2]);
            }
        }

        if (c + 1 < nch) {
            stageAB(smem + ((c + 1) & 1) * BUFSZ, (c + 1) << 5);
            __syncthreads();
        }
    }

    // epilogue
    float*  Cfz = Cf  ? Cf  + z * sC : nullptr;
    __half* Chz = COh ? COh + z * sC : nullptr;
    __half* Clz = COl ? COl + z * sC : nullptr;
#pragma unroll
    for (int mt = 0; mt < 4; mt++) {
        const int r0 = rowBase + wm * 64 + mt * 16 + (lane >> 2);
#pragma unroll
        for (int nt = 0; nt < 8; nt++) {
            const int c0 = colBase + wn * 64 + nt * 8 + (lane & 3) * 2;
            float v0 = acc[mt][nt][0] * alpha;
            float v1 = acc[mt][nt][1] * alpha;
            float v2 = acc[mt][nt][2] * alpha;
            float v3 = acc[mt][nt][3] * alpha;
            if (bias) {
                float b0 = __ldg(bias + c0), b1 = __ldg(bias + c0 + 1);
                v0 += b0; v1 += b1; v2 += b0; v3 += b1;
            }
            if (OUTSPLIT) {
                wr_split(Chz, Clz, (long)r0 * N + c0, v0, v1);
                wr_split(Chz, Clz, (long)(r0 + 8) * N + c0, v2, v3);
            } else if (!TRANSV) {
                *reinterpret_cast<float2*>(Cfz + (long)r0 * N + c0)       = make_float2(v0, v1);
                *reinterpret_cast<float2*>(Cfz + (long)(r0 + 8) * N + c0) = make_float2(v2, v3);
            } else {
                const int b0i = r0 >> 11, s0 = r0 & 2047;
                const int b1i = (r0 + 8) >> 11, s1 = (r0 + 8) & 2047;
                float* t0 = Cfz + (long)b0i * (HH * (long)SS) + s0;
                float* t1 = Cfz + (long)b1i * (HH * (long)SS) + s1;
                t0[(long)c0 * SS] = v0;       t0[(long)(c0 + 1) * SS] = v1;
                t1[(long)c0 * SS] = v2;       t1[(long)(c0 + 1) * SS] = v3;
            }
        }
    }
}

// ---------------- split softmax over QUERY axis ----------------
__global__ __launch_bounds__(256) void softmax_part(const float* __restrict__ sc,
                                                    float* __restrict__ pm, float* __restrict__ ps)
{
    const int col = blockIdx.x * 256 + threadIdx.x;
    const int seg = blockIdx.y, b = blockIdx.z;
    const float* p = sc + (long)b * SS * SS + (long)seg * 256 * SS + col;
    float m = -INFINITY, s = 0.f;
#pragma unroll 4
    for (int r = 0; r < 256; r++) {
        float v = p[(long)r * SS];
        float nm = fmaxf(m, v);
        s = s * __expf(m - nm) + __expf(v - nm);
        m = nm;
    }
    pm[((long)b * 8 + seg) * SS + col] = m;
    ps[((long)b * 8 + seg) * SS + col] = s;
}

__global__ __launch_bounds__(256) void softmax_comb(const float* __restrict__ pm,
                                                    const float* __restrict__ ps,
                                                    float* __restrict__ cm, float* __restrict__ ci)
{
    const int i = blockIdx.x * 256 + threadIdx.x;
    const int b = i >> 11, col = i & 2047;
    float M = -INFINITY;
#pragma unroll
    for (int s = 0; s < 8; s++) M = fmaxf(M, pm[((long)b * 8 + s) * SS + col]);
    float S = 0.f;
#pragma unroll
    for (int s = 0; s < 8; s++)
        S += ps[((long)b * 8 + s) * SS + col] * __expf(pm[((long)b * 8 + s) * SS + col] - M);
    cm[i] = M;
    ci[i] = 1.f / S;
}

// ---------------- launch ----------------
template <typename T>
static T* sym_addr(const void* sym) {
    void* p = nullptr;
    cudaGetSymbolAddress(&p, sym);
    return reinterpret_cast<T*>(p);
}

extern "C" void kernel_launch(void* const* d_in, const int* in_sizes, int n_in,
                              void* d_out, int out_size)
{
    const float* query = (const float*)d_in[0];
    const float* key   = (const float*)d_in[1];
    const float* value = (const float*)d_in[2];
    const float* Wq    = (const float*)d_in[3];
    const float* bq    = (const float*)d_in[4];
    const float* Wk    = (const float*)d_in[5];
    const float* bk    = (const float*)d_in[6];
    const float* Wv    = (const float*)d_in[7];
    const float* bv    = (const float*)d_in[8];
    const float* Wo    = (const float*)d_in[9];
    const float* bo    = (const float*)d_in[10];
    float* out = (float*)d_out;

    float* vT  = sym_addr<float>(g_vT);
    float* sc  = sym_addr<float>(g_sc);
    float* ctx = sym_addr<float>(g_ctx);
    __half* qh = sym_addr<__half>(g_qh);  __half* ql = sym_addr<__half>(g_ql);
    __half* kh = sym_addr<__half>(g_kh);  __half* kl = sym_addr<__half>(g_kl);
    __half* Wqh = sym_addr<__half>(s_Wqh); __half* Wql = sym_addr<__half>(s_Wql);
    __half* Wkh = sym_addr<__half>(s_Wkh); __half* Wkl = sym_addr<__half>(s_Wkl);
    __half* Wvh = sym_addr<__half>(s_Wvh); __half* Wvl = sym_addr<__half>(s_Wvl);
    __half* Woh = sym_addr<__half>(s_Woh); __half* Wol = sym_addr<__half>(s_Wol);
    float* pm = sym_addr<float>(g_pm);  float* ps = sym_addr<float>(g_ps);
    float* cm = sym_addr<float>(g_colM); float* ci = sym_addr<float>(g_colI);

    cudaFuncSetAttribute(gemm_hmma<3,0,0,1,1,0>, cudaFuncAttributeMaxDynamicSharedMemorySize, SMEM_SZ);
    cudaFuncSetAttribute(gemm_hmma<2,1,0,1,0,0>, cudaFuncAttributeMaxDynamicSharedMemorySize, SMEM_SZ);
    cudaFuncSetAttribute(gemm_hmma<2,0,1,1,0,0>, cudaFuncAttributeMaxDynamicSharedMemorySize, SMEM_SZ);
    cudaFuncSetAttribute(gemm_hmma<2,0,0,0,0,1>, cudaFuncAttributeMaxDynamicSharedMemorySize, SMEM_SZ);
    cudaFuncSetAttribute(gemm_hmma<2,0,0,1,0,0>, cudaFuncAttributeMaxDynamicSharedMemorySize, SMEM_SZ);

    const int M = BB * SS;   // 8192

    // 0) split all 4 weights in ONE launch
    const int nW4 = HH * DD / 4;
    split_w4<<<dim3(nW4 / 256, 4), 256>>>(
        (const float4*)Wq, (__half2*)Wqh, (__half2*)Wql,
        (const float4*)Wk, (__half2*)Wkh, (__half2*)Wkl,
        (const float4*)Wv, (__half2*)Wvh, (__half2*)Wvl,
        (const float4*)Wo, (__half2*)Woh, (__half2*)Wol, nW4);

    // 1) Projections: A = fp32 input, B = pre-split weights.
    dim3 gp(HH / 256, M / 128, 1);
    gemm_hmma<3,0,0,1,1,0><<<gp, 256, SMEM_SZ>>>(query, nullptr, nullptr, nullptr, Wqh, Wql,
                                                 bq, nullptr, qh, ql, nullptr, nullptr,
                                                 M, HH, DD, 0, 0, 0, 1.f);
    gemm_hmma<3,0,0,1,1,0><<<gp, 256, SMEM_SZ>>>(key, nullptr, nullptr, nullptr, Wkh, Wkl,
                                                 bk, nullptr, kh, kl, nullptr, nullptr,
                                                 M, HH, DD, 0, 0, 0, 1.f);
    gemm_hmma<2,1,0,1,0,0><<<gp, 256, SMEM_SZ>>>(value, nullptr, nullptr, nullptr, Wvh, Wvl,
                                                 bv, vT, nullptr, nullptr, nullptr, nullptr,
                                                 M, HH, DD, 0, 0, 0, 1.f);

    // 2) Scores: both operands pre-split; 2-pass (hiQ*hiK + hiQ*loK).
    //    Dropped loQ*hiK term: ~5.6e-4 absolute score error, within rel_err budget.
    dim3 gs(SS / 256, SS / 128, BB);
    gemm_hmma<2,0,1,1,0,0><<<gs, 256, SMEM_SZ>>>(nullptr, qh, ql, nullptr, kh, kl,
                                                 nullptr, sc, nullptr, nullptr, nullptr, nullptr,
                                                 SS, SS, HH,
                                                 (long)SS * HH, (long)SS * HH, (long)SS * SS, SCALEF);

    // 3) Softmax stats over the query axis (normalization fused into ctx GEMM)
    softmax_part<<<dim3(SS / 256, 8, BB), 256>>>(sc, pm, ps);
    softmax_comb<<<dim3(BB * SS / 256), 256>>>(pm, ps, cm, ci);

    // 4) Context with fused softmax: A-stage exp(sc - cm[k]), B-stage vT*ci[k]; 2-pass
    dim3 gc(HH / 256, SS / 128, BB);
    gemm_hmma<2,0,0,0,0,1><<<gc, 256, SMEM_SZ>>>(sc, nullptr, nullptr, vT, nullptr, nullptr,
                                                 nullptr, ctx, nullptr, nullptr, cm, ci,
                                                 SS, HH, SS,
                                                 (long)SS * SS, (long)HH * SS, (long)SS * HH, 1.f);

    // 5) Output projection: B = pre-split Wo, 2-pass, fp32 out + bias
    dim3 go(DD / 256, M / 128, 1);
    gemm_hmma<2,0,0,1,0,0><<<go, 256, SMEM_SZ>>>(ctx, nullptr, nullptr, nullptr, Woh, Wol,
                                                 bo, out, nullptr, nullptr, nullptr, nullptr,
                                                 M, DD, HH, 0, 0, 0, 1.f);
}

// round 17
// speedup vs baseline: 1.3774x; 1.0805x over previous
#include <cuda_runtime.h>
#include <cuda_fp16.h>
#include <cstdint>
#include <math.h>

#define BB 4
#define SS 2048
#define DD 1024
#define HH 1024
#define SCALEF 0.125f
#define MR (BB * SS)          // 8192

// ---------------- scratch (allocation-free rule) ----------------
__device__ float g_vT[BB * HH * SS];     // transposed V: [b][h][s]
__device__ float g_sc[BB * SS * SS];
__device__ float g_ctx[BB * SS * HH];
__device__ __align__(16) __half g_qh[MR * HH], g_ql[MR * HH];
__device__ __align__(16) __half g_kh[MR * HH], g_kl[MR * HH];
__device__ __align__(16) __half s_Wqh[HH * DD], s_Wql[HH * DD];
__device__ __align__(16) __half s_Wkh[HH * DD], s_Wkl[HH * DD];
__device__ __align__(16) __half s_Wvh[HH * DD], s_Wvl[HH * DD];
__device__ __align__(16) __half s_Woh[DD * HH], s_Wol[DD * HH];
__device__ float g_pm[BB * 8 * SS];
__device__ float g_ps[BB * 8 * SS];
__device__ float g_colM[BB * SS];
__device__ float g_colI[BB * SS];

// ---------------- helpers ----------------
__device__ __forceinline__ uint32_t smem_u32(const void* p) {
    uint32_t a;
    asm("{ .reg .u64 t; cvta.to.shared.u64 t, %1; cvt.u32.u64 %0, t; }" : "=r"(a) : "l"(p));
    return a;
}

#define LDSM4(r, a) \
    asm volatile("ldmatrix.sync.aligned.m8n8.x4.shared.b16 {%0,%1,%2,%3}, [%4];" \
        : "=r"((r)[0]), "=r"((r)[1]), "=r"((r)[2]), "=r"((r)[3]) : "r"(a))

__device__ __forceinline__ void mma16816(float* c, const uint32_t* a, const uint32_t* b) {
    asm volatile("mma.sync.aligned.m16n8k16.row.col.f32.f16.f16.f32 "
        "{%0,%1,%2,%3}, {%4,%5,%6,%7}, {%8,%9}, {%0,%1,%2,%3};"
        : "+f"(c[0]), "+f"(c[1]), "+f"(c[2]), "+f"(c[3])
        : "r"(a[0]), "r"(a[1]), "r"(a[2]), "r"(a[3]), "r"(b[0]), "r"(b[1]));
}

// split fp32x4 into hi fp16x4 + lo fp16x4 (exact residual)
__device__ __forceinline__ void cvt_split(float4 v, uint32_t& h01, uint32_t& h23,
                                          uint32_t& l01, uint32_t& l23) {
    __half2 a = __floats2half2_rn(v.x, v.y);
    __half2 b = __floats2half2_rn(v.z, v.w);
    float r0 = v.x - __half2float(__low2half(a));
    float r1 = v.y - __half2float(__high2half(a));
    float r2 = v.z - __half2float(__low2half(b));
    float r3 = v.w - __half2float(__high2half(b));
    __half2 c = __floats2half2_rn(r0, r1);
    __half2 d = __floats2half2_rn(r2, r3);
    h01 = *reinterpret_cast<uint32_t*>(&a);
    h23 = *reinterpret_cast<uint32_t*>(&b);
    l01 = *reinterpret_cast<uint32_t*>(&c);
    l23 = *reinterpret_cast<uint32_t*>(&d);
}
__device__ __forceinline__ void cvt_hi(float4 v, uint32_t& h01, uint32_t& h23) {
    __half2 a = __floats2half2_rn(v.x, v.y);
    __half2 b = __floats2half2_rn(v.z, v.w);
    h01 = *reinterpret_cast<uint32_t*>(&a);
    h23 = *reinterpret_cast<uint32_t*>(&b);
}
__device__ __forceinline__ void wr_split(__half* H, __half* L, long idx, float v0, float v1) {
    __half2 h = __floats2half2_rn(v0, v1);
    __half2 l = __floats2half2_rn(v0 - __low2float(h), v1 - __high2float(h));
    *reinterpret_cast<__half2*>(H + idx) = h;
    *reinterpret_cast<__half2*>(L + idx) = l;
}

// ---------------- fp32 -> hi/lo fp16 split: all 4 weights, one launch ----------------
__global__ __launch_bounds__(256) void split_w4(
    const float4* __restrict__ w0, __half2* __restrict__ h0p, __half2* __restrict__ l0p,
    const float4* __restrict__ w1, __half2* __restrict__ h1p, __half2* __restrict__ l1p,
    const float4* __restrict__ w2, __half2* __restrict__ h2p, __half2* __restrict__ l2p,
    const float4* __restrict__ w3, __half2* __restrict__ h3p, __half2* __restrict__ l3p,
    int n4)
{
    const float4* x; __half2* hi; __half2* lo;
    switch (blockIdx.y) {
        case 0: x = w0; hi = h0p; lo = l0p; break;
        case 1: x = w1; hi = h1p; lo = l1p; break;
        case 2: x = w2; hi = h2p; lo = l2p; break;
        default: x = w3; hi = h3p; lo = l3p; break;
    }
    int i = blockIdx.x * 256 + threadIdx.x;
    if (i >= n4) return;
    float4 v = x[i];
    __half2 a = __floats2half2_rn(v.x, v.y);
    __half2 b = __floats2half2_rn(v.z, v.w);
    __half2 c = __floats2half2_rn(v.x - __low2float(a), v.y - __high2float(a));
    __half2 d = __floats2half2_rn(v.z - __low2float(b), v.w - __high2float(b));
    hi[2 * i] = a; hi[2 * i + 1] = b;
    lo[2 * i] = c; lo[2 * i + 1] = d;
}

// ---------------- HMMA split-fp16 NT GEMM, tile 128x256x32 ----------------
// C[m,n] = alpha * sum_k A[m,k] * B[n,k] (+ bias[n])
// 8 warps (2m x 4n), warp tile 64x64; pass-major MMA ordering.
// PASSES=3: hh + hl + lh.  PASSES=2: hh + hl.  PASSES=1: hh only (B hi-only).
// FUSESM: A = raw scores -> stage applies exp(a - cm[k]); B = vT -> stage applies *ci[k].
#define LROW 80
#define OFF_AL 10240              // A: 128 rows x 80B
#define OFF_BH 20480
#define OFF_BL 40960              // B: 256 rows x 80B
#define BUFSZ  61440
#define SMEM_SZ (2 * BUFSZ)

template <int PASSES, int TRANSV, int APRE, int BPRE, int OUTSPLIT, int FUSESM>
__global__ __launch_bounds__(256, 1) void gemm_hmma(
    const float* __restrict__ Af, const __half* __restrict__ APh, const __half* __restrict__ APl,
    const float* __restrict__ Bf, const __half* __restrict__ BPh, const __half* __restrict__ BPl,
    const float* __restrict__ bias, float* __restrict__ Cf,
    __half* __restrict__ COh, __half* __restrict__ COl,
    const float* __restrict__ cmp, const float* __restrict__ cip,
    int M, int N, int K, long sA, long sB, long sC, float alpha)
{
    extern __shared__ char smem[];
    const uint32_t sb = smem_u32(smem);
    const int tid  = threadIdx.x;
    const int lane = tid & 31;
    const int wid  = tid >> 5;
    const int wm   = wid & 1;
    const int wn   = wid >> 1;
    const long z   = blockIdx.z;

    const int rowBase = blockIdx.y * 128;
    const int colBase = blockIdx.x * 256;

    const int ldRow = tid >> 3;           // fp32 staging coords
    const int ldC4  = (tid & 7) << 2;

    const float*  Apf = nullptr; const __half *Aph = nullptr, *Apl = nullptr;
    const float*  Bpf = nullptr; const __half *Bph = nullptr, *Bpl = nullptr;
    if (!APRE) Apf = Af + z * sA + (long)rowBase * K;
    else { Aph = APh + z * sA + (long)rowBase * K;
           if (PASSES == 3) Apl = APl + z * sA + (long)rowBase * K; }
    if (!BPRE) Bpf = Bf + z * sB + (long)colBase * K;
    else { Bph = BPh + z * sB + (long)colBase * K;
           if (PASSES >= 2) Bpl = BPl + z * sB + (long)colBase * K; }
    const float* cmz = FUSESM ? cmp + z * SS : nullptr;
    const float* ciz = FUSESM ? cip + z * SS : nullptr;

    float4 pa[4], pb[8];
    uint4  pah[2], pal[2], pbh[4], pbl[4];

    auto loadAB = [&](int k0) {
        if (!APRE) {
#pragma unroll
            for (int i = 0; i < 4; i++)
                pa[i] = *reinterpret_cast<const float4*>(Apf + (long)(ldRow + i * 32) * K + k0 + ldC4);
        } else {
#pragma unroll
            for (int h = 0; h < 2; h++) {
                int idx = tid + (h << 8);
                long go = (long)(idx >> 2) * K + k0 + ((idx & 3) << 3);
                pah[h] = *reinterpret_cast<const uint4*>(Aph + go);
                if (PASSES == 3) pal[h] = *reinterpret_cast<const uint4*>(Apl + go);
            }
        }
        if (!BPRE) {
#pragma unroll
            for (int i = 0; i < 8; i++)
                pb[i] = *reinterpret_cast<const float4*>(Bpf + (long)(ldRow + i * 32) * K + k0 + ldC4);
        } else {
#pragma unroll
            for (int h = 0; h < 4; h++) {
                int idx = tid + (h << 8);
                long go = (long)(idx >> 2) * K + k0 + ((idx & 3) << 3);
                pbh[h] = *reinterpret_cast<const uint4*>(Bph + go);
                if (PASSES >= 2) pbl[h] = *reinterpret_cast<const uint4*>(Bpl + go);
            }
        }
    };

    auto stageAB = [&](char* dst, int k0) {
        if (!APRE) {
            float4 cmv;
            if (FUSESM) cmv = *reinterpret_cast<const float4*>(cmz + k0 + ldC4);
#pragma unroll
            for (int i = 0; i < 4; i++) {
                float4 v = pa[i];
                if (FUSESM) {
                    v.x = __expf(v.x - cmv.x);
                    v.y = __expf(v.y - cmv.y);
                    v.z = __expf(v.z - cmv.z);
                    v.w = __expf(v.w - cmv.w);
                }
                uint32_t h01, h23, l01, l23;
                int off = (ldRow + i * 32) * LROW + ldC4 * 2;
                if (PASSES == 3) {
                    cvt_split(v, h01, h23, l01, l23);
                    *reinterpret_cast<uint2*>(dst + off)          = make_uint2(h01, h23);
                    *reinterpret_cast<uint2*>(dst + off + OFF_AL) = make_uint2(l01, l23);
                } else {
                    cvt_hi(v, h01, h23);
                    *reinterpret_cast<uint2*>(dst + off)          = make_uint2(h01, h23);
                }
            }
        } else {
#pragma unroll
            for (int h = 0; h < 2; h++) {
                int idx = tid + (h << 8);
                int off = (idx >> 2) * LROW + ((idx & 3) << 4);
                *reinterpret_cast<uint4*>(dst + off) = pah[h];
                if (PASSES == 3) *reinterpret_cast<uint4*>(dst + off + OFF_AL) = pal[h];
            }
        }
        if (!BPRE) {
            float4 civ;
            if (FUSESM) civ = *reinterpret_cast<const float4*>(ciz + k0 + ldC4);
#pragma unroll
            for (int i = 0; i < 8; i++) {
                float4 v = pb[i];
                if (FUSESM) { v.x *= civ.x; v.y *= civ.y; v.z *= civ.z; v.w *= civ.w; }
                uint32_t h01, h23, l01, l23;
                int off = (ldRow + i * 32) * LROW + ldC4 * 2;
                if (PASSES >= 2) {
                    cvt_split(v, h01, h23, l01, l23);
                    *reinterpret_cast<uint2*>(dst + off + OFF_BH) = make_uint2(h01, h23);
                    *reinterpret_cast<uint2*>(dst + off + OFF_BL) = make_uint2(l01, l23);
                } else {
                    cvt_hi(v, h01, h23);
                    *reinterpret_cast<uint2*>(dst + off + OFF_BH) = make_uint2(h01, h23);
                }
            }
        } else {
#pragma unroll
            for (int h = 0; h < 4; h++) {
                int idx = tid + (h << 8);
                int off = (idx >> 2) * LROW + ((idx & 3) << 4);
                *reinterpret_cast<uint4*>(dst + off + OFF_BH) = pbh[h];
                if (PASSES >= 2) *reinterpret_cast<uint4*>(dst + off + OFF_BL) = pbl[h];
            }
        }
    };

    float acc[4][8][4] = {};
    const int nch = K >> 5;

    loadAB(0);
    stageAB(smem, 0);
    __syncthreads();

    for (int c = 0; c < nch; c++) {
        if (c + 1 < nch) loadAB((c + 1) << 5);

        const uint32_t base = sb + (c & 1) * BUFSZ;
#pragma unroll
        for (int ks = 0; ks < 2; ks++) {
            uint32_t ah[4][4], al[4][4], bh[4][4], bl[4][4];
            const int kcA = ks * 16 + ((lane >> 4) << 3);
            const int mr  = wm * 64 + (lane & 15);
#pragma unroll
            for (int mt = 0; mt < 4; mt++) {
                uint32_t ad = base + (mr + mt * 16) * LROW + kcA * 2;
                LDSM4(ah[mt], ad);
                if (PASSES == 3) LDSM4(al[mt], ad + OFF_AL);
            }
            const int nr  = wn * 64 + (lane & 7) + ((lane >> 4) << 3);
            const int kcB = ks * 16 + (((lane >> 3) & 1) << 3);
#pragma unroll
            for (int np = 0; np < 4; np++) {
                uint32_t bd = base + OFF_BH + (nr + np * 16) * LROW + kcB * 2;
                LDSM4(bh[np], bd);
                if (PASSES >= 2) LDSM4(bl[np], bd + (OFF_BL - OFF_BH));
            }
            // pass-major ordering: consecutive MMAs never share an accumulator
#pragma unroll
            for (int mt = 0; mt < 4; mt++)
#pragma unroll
                for (int nt = 0; nt < 8; nt++)
                    mma16816(acc[mt][nt], ah[mt], &bh[nt >> 1][(nt & 1) * 2]);
            if (PASSES >= 2) {
#pragma unroll
                for (int mt = 0; mt < 4; mt++)
#pragma unroll
                    for (int nt = 0; nt < 8; nt++)
                        mma16816(acc[mt][nt], ah[mt], &bl[nt >> 1][(nt & 1) * 2]);
            }
            if (PASSES == 3) {
#pragma unroll
                for (int mt = 0; mt < 4; mt++)
#pragma unroll
                    for (int nt = 0; nt < 8; nt++)
                        mma16816(acc[mt][nt], al[mt], &bh[nt >> 1][(nt & 1) * 2]);
            }
        }

        if (c + 1 < nch) {
            stageAB(smem + ((c + 1) & 1) * BUFSZ, (c + 1) << 5);
            __syncthreads();
        }
    }

    // epilogue
    float*  Cfz = Cf  ? Cf  + z * sC : nullptr;
    __half* Chz = COh ? COh + z * sC : nullptr;
    __half* Clz = COl ? COl + z * sC : nullptr;
#pragma unroll
    for (int mt = 0; mt < 4; mt++) {
        const int r0 = rowBase + wm * 64 + mt * 16 + (lane >> 2);
#pragma unroll
        for (int nt = 0; nt < 8; nt++) {
            const int c0 = colBase + wn * 64 + nt * 8 + (lane & 3) * 2;
            float v0 = acc[mt][nt][0] * alpha;
            float v1 = acc[mt][nt][1] * alpha;
            float v2 = acc[mt][nt][2] * alpha;
            float v3 = acc[mt][nt][3] * alpha;
            if (bias) {
                float b0 = __ldg(bias + c0), b1 = __ldg(bias + c0 + 1);
                v0 += b0; v1 += b1; v2 += b0; v3 += b1;
            }
            if (OUTSPLIT) {
                wr_split(Chz, Clz, (long)r0 * N + c0, v0, v1);
                wr_split(Chz, Clz, (long)(r0 + 8) * N + c0, v2, v3);
            } else if (!TRANSV) {
                *reinterpret_cast<float2*>(Cfz + (long)r0 * N + c0)       = make_float2(v0, v1);
                *reinterpret_cast<float2*>(Cfz + (long)(r0 + 8) * N + c0) = make_float2(v2, v3);
            } else {
                const int b0i = r0 >> 11, s0 = r0 & 2047;
                const int b1i = (r0 + 8) >> 11, s1 = (r0 + 8) & 2047;
                float* t0 = Cfz + (long)b0i * (HH * (long)SS) + s0;
                float* t1 = Cfz + (long)b1i * (HH * (long)SS) + s1;
                t0[(long)c0 * SS] = v0;       t0[(long)(c0 + 1) * SS] = v1;
                t1[(long)c0 * SS] = v2;       t1[(long)(c0 + 1) * SS] = v3;
            }
        }
    }
}

// ---------------- split softmax over QUERY axis ----------------
__global__ __launch_bounds__(256) void softmax_part(const float* __restrict__ sc,
                                                    float* __restrict__ pm, float* __restrict__ ps)
{
    const int col = blockIdx.x * 256 + threadIdx.x;
    const int seg = blockIdx.y, b = blockIdx.z;
    const float* p = sc + (long)b * SS * SS + (long)seg * 256 * SS + col;
    float m = -INFINITY, s = 0.f;
#pragma unroll 4
    for (int r = 0; r < 256; r++) {
        float v = p[(long)r * SS];
        float nm = fmaxf(m, v);
        s = s * __expf(m - nm) + __expf(v - nm);
        m = nm;
    }
    pm[((long)b * 8 + seg) * SS + col] = m;
    ps[((long)b * 8 + seg) * SS + col] = s;
}

__global__ __launch_bounds__(256) void softmax_comb(const float* __restrict__ pm,
                                                    const float* __restrict__ ps,
                                                    float* __restrict__ cm, float* __restrict__ ci)
{
    const int i = blockIdx.x * 256 + threadIdx.x;
    const int b = i >> 11, col = i & 2047;
    float M = -INFINITY;
#pragma unroll
    for (int s = 0; s < 8; s++) M = fmaxf(M, pm[((long)b * 8 + s) * SS + col]);
    float S = 0.f;
#pragma unroll
    for (int s = 0; s < 8; s++)
        S += ps[((long)b * 8 + s) * SS + col] * __expf(pm[((long)b * 8 + s) * SS + col] - M);
    cm[i] = M;
    ci[i] = 1.f / S;
}

// ---------------- launch ----------------
template <typename T>
static T* sym_addr(const void* sym) {
    void* p = nullptr;
    cudaGetSymbolAddress(&p, sym);
    return reinterpret_cast<T*>(p);
}

extern "C" void kernel_launch(void* const* d_in, const int* in_sizes, int n_in,
                              void* d_out, int out_size)
{
    const float* query = (const float*)d_in[0];
    const float* key   = (const float*)d_in[1];
    const float* value = (const float*)d_in[2];
    const float* Wq    = (const float*)d_in[3];
    const float* bq    = (const float*)d_in[4];
    const float* Wk    = (const float*)d_in[5];
    const float* bk    = (const float*)d_in[6];
    const float* Wv    = (const float*)d_in[7];
    const float* bv    = (const float*)d_in[8];
    const float* Wo    = (const float*)d_in[9];
    const float* bo    = (const float*)d_in[10];
    float* out = (float*)d_out;

    float* vT  = sym_addr<float>(g_vT);
    float* sc  = sym_addr<float>(g_sc);
    float* ctx = sym_addr<float>(g_ctx);
    __half* qh = sym_addr<__half>(g_qh);  __half* ql = sym_addr<__half>(g_ql);
    __half* kh = sym_addr<__half>(g_kh);  __half* kl = sym_addr<__half>(g_kl);
    __half* Wqh = sym_addr<__half>(s_Wqh); __half* Wql = sym_addr<__half>(s_Wql);
    __half* Wkh = sym_addr<__half>(s_Wkh); __half* Wkl = sym_addr<__half>(s_Wkl);
    __half* Wvh = sym_addr<__half>(s_Wvh); __half* Wvl = sym_addr<__half>(s_Wvl);
    __half* Woh = sym_addr<__half>(s_Woh); __half* Wol = sym_addr<__half>(s_Wol);
    float* pm = sym_addr<float>(g_pm);  float* ps = sym_addr<float>(g_ps);
    float* cm = sym_addr<float>(g_colM); float* ci = sym_addr<float>(g_colI);

    cudaFuncSetAttribute(gemm_hmma<3,0,0,1,1,0>, cudaFuncAttributeMaxDynamicSharedMemorySize, SMEM_SZ);
    cudaFuncSetAttribute(gemm_hmma<2,1,0,1,0,0>, cudaFuncAttributeMaxDynamicSharedMemorySize, SMEM_SZ);
    cudaFuncSetAttribute(gemm_hmma<2,0,1,1,0,0>, cudaFuncAttributeMaxDynamicSharedMemorySize, SMEM_SZ);
    cudaFuncSetAttribute(gemm_hmma<1,0,0,0,0,1>, cudaFuncAttributeMaxDynamicSharedMemorySize, SMEM_SZ);
    cudaFuncSetAttribute(gemm_hmma<2,0,0,1,0,0>, cudaFuncAttributeMaxDynamicSharedMemorySize, SMEM_SZ);

    const int M = BB * SS;   // 8192

    // 0) split all 4 weights in ONE launch
    const int nW4 = HH * DD / 4;
    split_w4<<<dim3(nW4 / 256, 4), 256>>>(
        (const float4*)Wq, (__half2*)Wqh, (__half2*)Wql,
        (const float4*)Wk, (__half2*)Wkh, (__half2*)Wkl,
        (const float4*)Wv, (__half2*)Wvh, (__half2*)Wvl,
        (const float4*)Wo, (__half2*)Woh, (__half2*)Wol, nW4);

    // 1) Projections: A = fp32 input, B = pre-split weights.
    dim3 gp(HH / 256, M / 128, 1);
    gemm_hmma<3,0,0,1,1,0><<<gp, 256, SMEM_SZ>>>(query, nullptr, nullptr, nullptr, Wqh, Wql,
                                                 bq, nullptr, qh, ql, nullptr, nullptr,
                                                 M, HH, DD, 0, 0, 0, 1.f);
    gemm_hmma<3,0,0,1,1,0><<<gp, 256, SMEM_SZ>>>(key, nullptr, nullptr, nullptr, Wkh, Wkl,
                                                 bk, nullptr, kh, kl, nullptr, nullptr,
                                                 M, HH, DD, 0, 0, 0, 1.f);
    gemm_hmma<2,1,0,1,0,0><<<gp, 256, SMEM_SZ>>>(value, nullptr, nullptr, nullptr, Wvh, Wvl,
                                                 bv, vT, nullptr, nullptr, nullptr, nullptr,
                                                 M, HH, DD, 0, 0, 0, 1.f);

    // 2) Scores: both operands pre-split; 2-pass (hiQ*hiK + hiQ*loK).
    dim3 gs(SS / 256, SS / 128, BB);
    gemm_hmma<2,0,1,1,0,0><<<gs, 256, SMEM_SZ>>>(nullptr, qh, ql, nullptr, kh, kl,
                                                 nullptr, sc, nullptr, nullptr, nullptr, nullptr,
                                                 SS, SS, HH,
                                                 (long)SS * HH, (long)SS * HH, (long)SS * SS, SCALEF);

    // 3) Softmax stats over the query axis (normalization fused into ctx GEMM)
    softmax_part<<<dim3(SS / 256, 8, BB), 256>>>(sc, pm, ps);
    softmax_comb<<<dim3(BB * SS / 256), 256>>>(pm, ps, cm, ci);

    // 4) Context with fused softmax: 1-pass (attn-hi * V-hi).
    //    Dropped V-lo term: ~2.8e-4 relative, quadrature total ~6.4e-4 < 1e-3.
    dim3 gc(HH / 256, SS / 128, BB);
    gemm_hmma<1,0,0,0,0,1><<<gc, 256, SMEM_SZ>>>(sc, nullptr, nullptr, vT, nullptr, nullptr,
                                                 nullptr, ctx, nullptr, nullptr, cm, ci,
                                                 SS, HH, SS,
                                                 (long)SS * SS, (long)HH * SS, (long)SS * HH, 1.f);

    // 5) Output projection: B = pre-split Wo, 2-pass, fp32 out + bias
    dim3 go(DD / 256, M / 128, 1);
    gemm_hmma<2,0,0,1,0,0><<<go, 256, SMEM_SZ>>>(ctx, nullptr, nullptr, nullptr, Woh, Wol,
                                                 bo, out, nullptr, nullptr, nullptr, nullptr,
                                                 M, DD, HH, 0, 0, 0, 1.f);
}